// round 1
// baseline (speedup 1.0000x reference)
#include <cuda_runtime.h>
#include <cuda_bf16.h>
#include <math.h>

// Problem constants
#define BATCH 128
#define NNODE 1024
#define RTOT  (BATCH * NNODE)   // 131072
#define EEDGE 4096
#define DIM   40
#define SLEN  4
#define HID   128

// ---------------- scratch (__device__ globals; no allocation allowed) ----------------
__device__ float g_xl[(size_t)RTOT * HID];
__device__ float g_xr[(size_t)RTOT * HID];
__device__ float g_w2t[3 * 256 * 40];     // ffn_w2 transposed: [layer][k][d]
__device__ int   g_csr_off[NNODE + 1];
__device__ int   g_csr_src[EEDGE];

// ---------------- prep: transpose ffn_w2 ----------------
__global__ void prep_w2t_kernel(const float* __restrict__ w2) {
    int i = blockIdx.x * blockDim.x + threadIdx.x;
    if (i < 3 * 256 * 40) {
        int d = i % 40;
        int k = (i / 40) % 256;
        int l = i / (40 * 256);
        g_w2t[i] = w2[(size_t)l * 40 * 256 + (size_t)d * 256 + k];
    }
}

// ---------------- CSR build (single block, deterministic) ----------------
__global__ void csr_build_kernel(const int* __restrict__ edge_index) {
    __shared__ int cnt[NNODE];
    __shared__ int off[NNODE + 1];
    __shared__ int cur[NNODE];
    int t = threadIdx.x;            // 1024 threads
    cnt[t] = 0;
    __syncthreads();
    for (int e = t; e < EEDGE; e += 1024) {
        int dst = edge_index[EEDGE + e];
        atomicAdd(&cnt[dst], 1);
    }
    __syncthreads();
    if (t == 0) {
        off[0] = 0;
        for (int i = 0; i < NNODE; ++i) off[i + 1] = off[i] + cnt[i];
    }
    __syncthreads();
    cur[t] = off[t];
    __syncthreads();
    for (int e = t; e < EEDGE; e += 1024) {
        int src = edge_index[e];
        int dst = edge_index[EEDGE + e];
        int pos = atomicAdd(&cur[dst], 1);
        g_csr_src[pos] = src;
    }
    g_csr_off[t] = off[t];
    if (t == 0) g_csr_off[NNODE] = off[NNODE];
    __syncthreads();
    // canonicalize bucket order (value sort) -> deterministic summation order
    int lo = off[t], hi = off[t + 1];
    for (int i = lo + 1; i < hi; ++i) {
        int v = g_csr_src[i];
        int j = i - 1;
        while (j >= lo && g_csr_src[j] > v) { g_csr_src[j + 1] = g_csr_src[j]; --j; }
        g_csr_src[j + 1] = v;
    }
}

// ---------------- fused transformer + emb + xl/xr kernel ----------------
// Block: 64 threads = 16 rows x 4 tokens. The 4 token-threads of a row are
// consecutive lanes of one warp -> __syncwarp suffices.
#define TROWS 16
#define RSTRIDE 484   // per-row smem stride (484 % 32 == 4 -> conflict-free across rows)

__global__ __launch_bounds__(64) void tf_kernel(
    const float* __restrict__ obs, const float* __restrict__ pe,
    const float* __restrict__ wqkv_all, const float* __restrict__ bqkv_all,
    const float* __restrict__ wo_all,   const float* __restrict__ bo_all,
    const float* __restrict__ w1_all,   const float* __restrict__ b1_all,
    const float* __restrict__ b2_all,
    const float* __restrict__ ln1g_all, const float* __restrict__ ln1b_all,
    const float* __restrict__ ln2g_all, const float* __restrict__ ln2b_all,
    const float* __restrict__ Wemb1, const float* __restrict__ bemb1,
    const float* __restrict__ Wemb2, const float* __restrict__ bemb2,
    const float* __restrict__ gwl, const float* __restrict__ gbl,
    const float* __restrict__ gwr, const float* __restrict__ gbr)
{
    __shared__ float sm[TROWS * RSTRIDE];
    const int tid = threadIdx.x;
    const int rowloc = tid >> 2;
    const int t = tid & 3;
    const int r = blockIdx.x * TROWS + rowloc;
    float* rs = sm + rowloc * RSTRIDE;

    const float* xrow = obs + (size_t)r * 200;

    float h[40];
#pragma unroll
    for (int d = 0; d < 40; ++d)
        h[d] = __ldg(xrow + t * 40 + d) + __ldg(pe + t * 40 + d);

    for (int L = 0; L < 3; ++L) {
        const float* wqkv = wqkv_all + L * 4800;
        const float* bqkv = bqkv_all + L * 120;
        // ---- QKV projection -> smem ----
        for (int kk = 0; kk < 120; ++kk) {
            float s = __ldg(bqkv + kk);
            const float4* w = (const float4*)(wqkv + kk * 40);
#pragma unroll
            for (int d4 = 0; d4 < 10; ++d4) {
                float4 wv = __ldg(w + d4);
                s += h[4*d4]*wv.x + h[4*d4+1]*wv.y + h[4*d4+2]*wv.z + h[4*d4+3]*wv.w;
            }
            rs[t * 121 + kk] = s;
        }
        __syncwarp();

        // ---- attention (causal, 2 heads of 20) ----
        float o[40];
        const float scale = 0.22360679774997896f;  // 1/sqrt(20)
#pragma unroll
        for (int hh = 0; hh < 2; ++hh) {
            float sc[4];
            float mx = -1e30f;
#pragma unroll
            for (int j = 0; j < 4; ++j) {
                if (j <= t) {
                    float s = 0.f;
#pragma unroll
                    for (int d = 0; d < 20; ++d)
                        s += rs[t*121 + hh*20 + d] * rs[j*121 + 40 + hh*20 + d];
                    sc[j] = s * scale;
                    mx = fmaxf(mx, sc[j]);
                }
            }
            float den = 0.f;
#pragma unroll
            for (int j = 0; j < 4; ++j) {
                if (j <= t) { sc[j] = expf(sc[j] - mx); den += sc[j]; }
                else sc[j] = 0.f;
            }
            float iden = 1.f / den;
#pragma unroll
            for (int d = 0; d < 20; ++d) {
                float a = 0.f;
#pragma unroll
                for (int j = 0; j < 4; ++j)
                    a += sc[j] * rs[j*121 + 80 + hh*20 + d];
                o[hh*20 + d] = a * iden;
            }
        }
        __syncwarp();   // all smem reads done; next layer may rewrite

        // ---- output projection + residual + LN1 ----
        const float* wo = wo_all + L * 1600;
        float nh[40];
#pragma unroll
        for (int d = 0; d < 40; ++d) {
            float s = __ldg(bo_all + L * 40 + d);
            const float4* w = (const float4*)(wo + d * 40);
#pragma unroll
            for (int e4 = 0; e4 < 10; ++e4) {
                float4 wv = __ldg(w + e4);
                s += o[4*e4]*wv.x + o[4*e4+1]*wv.y + o[4*e4+2]*wv.z + o[4*e4+3]*wv.w;
            }
            nh[d] = h[d] + s;
        }
        {
            float mean = 0.f;
#pragma unroll
            for (int d = 0; d < 40; ++d) mean += nh[d];
            mean *= (1.f / 40.f);
            float var = 0.f;
#pragma unroll
            for (int d = 0; d < 40; ++d) { float dv = nh[d] - mean; var += dv * dv; }
            var *= (1.f / 40.f);
            float rstd = rsqrtf(var + 1e-6f);
#pragma unroll
            for (int d = 0; d < 40; ++d)
                h[d] = (nh[d] - mean) * rstd * __ldg(ln1g_all + L*40 + d) + __ldg(ln1b_all + L*40 + d);
        }

        // ---- FFN (rank-1 over k, w2 pre-transposed) ----
        const float* w1  = w1_all + L * 10240;
        const float* w2t = g_w2t  + L * 10240;
        const float* b1  = b1_all + L * 256;
        float acc[40];
#pragma unroll
        for (int d = 0; d < 40; ++d) acc[d] = __ldg(b2_all + L * 40 + d);
        for (int k = 0; k < 256; ++k) {
            float u = __ldg(b1 + k);
            const float4* wa = (const float4*)(w1 + k * 40);
#pragma unroll
            for (int d4 = 0; d4 < 10; ++d4) {
                float4 wv = __ldg(wa + d4);
                u += h[4*d4]*wv.x + h[4*d4+1]*wv.y + h[4*d4+2]*wv.z + h[4*d4+3]*wv.w;
            }
            u = fmaxf(u, 0.f);
            const float4* wb = (const float4*)(w2t + k * 40);
#pragma unroll
            for (int d4 = 0; d4 < 10; ++d4) {
                float4 wv = __ldg(wb + d4);
                acc[4*d4]   += u * wv.x;
                acc[4*d4+1] += u * wv.y;
                acc[4*d4+2] += u * wv.z;
                acc[4*d4+3] += u * wv.w;
            }
        }
        {
#pragma unroll
            for (int d = 0; d < 40; ++d) nh[d] = h[d] + acc[d];
            float mean = 0.f;
#pragma unroll
            for (int d = 0; d < 40; ++d) mean += nh[d];
            mean *= (1.f / 40.f);
            float var = 0.f;
#pragma unroll
            for (int d = 0; d < 40; ++d) { float dv = nh[d] - mean; var += dv * dv; }
            var *= (1.f / 40.f);
            float rstd = rsqrtf(var + 1e-6f);
#pragma unroll
            for (int d = 0; d < 40; ++d)
                h[d] = (nh[d] - mean) * rstd * __ldg(ln2g_all + L*40 + d) + __ldg(ln2b_all + L*40 + d);
        }
    }

    // ---- emb1 / emb2 / xl / xr tail ----
    __syncwarp();
#pragma unroll
    for (int d = 0; d < 40; ++d) rs[t * 40 + d] = h[d];          // ret[0:160]
#pragma unroll
    for (int j = 0; j < 8; ++j)                                  // ret[160:192] = current_obs
        rs[160 + t * 8 + j] = __ldg(xrow + 160 + t * 8 + j);
    __syncwarp();

    for (int oi = 0; oi < 32; ++oi) {                            // emb1: 192 -> 128, relu
        int oo = t * 32 + oi;
        float s = __ldg(bemb1 + oo);
        const float4* w = (const float4*)(Wemb1 + (size_t)oo * 192);
#pragma unroll
        for (int j4 = 0; j4 < 48; ++j4) {
            float4 wv = __ldg(w + j4);
            s += rs[4*j4]*wv.x + rs[4*j4+1]*wv.y + rs[4*j4+2]*wv.z + rs[4*j4+3]*wv.w;
        }
        rs[192 + oo] = fmaxf(s, 0.f);
    }
    __syncwarp();

    for (int oi = 0; oi < 32; ++oi) {                            // emb2: 128 -> 128, relu
        int oo = t * 32 + oi;
        float s = __ldg(bemb2 + oo);
        const float4* w = (const float4*)(Wemb2 + (size_t)oo * 128);
#pragma unroll
        for (int j4 = 0; j4 < 32; ++j4) {
            float4 wv = __ldg(w + j4);
            s += rs[192+4*j4]*wv.x + rs[192+4*j4+1]*wv.y + rs[192+4*j4+2]*wv.z + rs[192+4*j4+3]*wv.w;
        }
        rs[320 + oo] = fmaxf(s, 0.f);
    }
    __syncwarp();

    for (int oi = 0; oi < 32; ++oi) {                            // xl / xr projections
        int oo = t * 32 + oi;
        float sl = __ldg(gbl + oo);
        float sr = __ldg(gbr + oo);
        const float4* wl = (const float4*)(gwl + (size_t)oo * 128);
        const float4* wr = (const float4*)(gwr + (size_t)oo * 128);
#pragma unroll
        for (int j4 = 0; j4 < 32; ++j4) {
            float4 a  = __ldg(wl + j4);
            float4 bv = __ldg(wr + j4);
            float e0 = rs[320+4*j4], e1 = rs[320+4*j4+1], e2 = rs[320+4*j4+2], e3 = rs[320+4*j4+3];
            sl += e0*a.x  + e1*a.y  + e2*a.z  + e3*a.w;
            sr += e0*bv.x + e1*bv.y + e2*bv.z + e3*bv.w;
        }
        g_xl[(size_t)r * 128 + oo] = sl;
        g_xr[(size_t)r * 128 + oo] = sr;
    }
}

// ---------------- GAT gather + final linear (warp per row, online softmax) ----------------
__global__ void gat_kernel(const float* __restrict__ gat_att,
                           const float* __restrict__ gat_bias,
                           const float* __restrict__ Wq,
                           const float* __restrict__ bq,
                           float* __restrict__ out)
{
    const int warp = (blockIdx.x * blockDim.x + threadIdx.x) >> 5;
    const int lane = threadIdx.x & 31;
    if (warp >= RTOT) return;
    const int r = warp;
    const int b = r >> 10;
    const int n = r & 1023;

    float xrv[4], attv[4], m[4], l[4], acc[4];
#pragma unroll
    for (int hh = 0; hh < 4; ++hh) {
        xrv[hh]  = g_xr[(size_t)r * 128 + hh * 32 + lane];
        attv[hh] = __ldg(gat_att + hh * 32 + lane);
        m[hh] = -1e30f; l[hh] = 0.f; acc[hh] = 0.f;
    }
    const int lo = g_csr_off[n], hi = g_csr_off[n + 1];
    for (int it = -1; it < hi - lo; ++it) {
        const int srcn = (it < 0) ? n : g_csr_src[lo + it];   // self-loop first, then sorted edges
        const float* xlp = g_xl + ((size_t)(b * 1024 + srcn)) * 128;
        float xlv[4], ev[4];
#pragma unroll
        for (int hh = 0; hh < 4; ++hh) {
            xlv[hh] = xlp[hh * 32 + lane];
            float mm = xlv[hh] + xrv[hh];
            mm = (mm > 0.f) ? mm : 0.2f * mm;                 // leaky_relu(0.2)
            float p = mm * attv[hh];
#pragma unroll
            for (int s = 16; s > 0; s >>= 1) p += __shfl_xor_sync(0xffffffffu, p, s);
            ev[hh] = p;
        }
#pragma unroll
        for (int hh = 0; hh < 4; ++hh) {
            float nm  = fmaxf(m[hh], ev[hh]);
            float pe_ = expf(ev[hh] - nm);
            float sc  = expf(m[hh] - nm);
            l[hh]   = l[hh] * sc + pe_;
            acc[hh] = acc[hh] * sc + pe_ * xlv[hh];
            m[hh] = nm;
        }
    }
    float h2[4];
#pragma unroll
    for (int hh = 0; hh < 4; ++hh)
        h2[hh] = acc[hh] / l[hh] + __ldg(gat_bias + hh * 32 + lane);

#pragma unroll
    for (int a = 0; a < 8; ++a) {
        float p = 0.f;
#pragma unroll
        for (int hh = 0; hh < 4; ++hh)
            p += h2[hh] * __ldg(Wq + a * 128 + hh * 32 + lane);
#pragma unroll
        for (int s = 16; s > 0; s >>= 1) p += __shfl_xor_sync(0xffffffffu, p, s);
        if (lane == 0) out[(size_t)r * 8 + a] = p + __ldg(bq + a);
    }
}

// ---------------- launch ----------------
extern "C" void kernel_launch(void* const* d_in, const int* in_sizes, int n_in,
                              void* d_out, int out_size) {
    const float* obs      = (const float*)d_in[0];
    const int*   edge_idx = (const int*)  d_in[1];
    const float* W_emb1   = (const float*)d_in[2];
    const float* b_emb1   = (const float*)d_in[3];
    const float* W_emb2   = (const float*)d_in[4];
    const float* b_emb2   = (const float*)d_in[5];
    const float* tf_wqkv  = (const float*)d_in[6];
    const float* tf_bqkv  = (const float*)d_in[7];
    const float* tf_wo    = (const float*)d_in[8];
    const float* tf_bo    = (const float*)d_in[9];
    const float* ffn_w1   = (const float*)d_in[10];
    const float* ffn_b1   = (const float*)d_in[11];
    const float* ffn_w2   = (const float*)d_in[12];
    const float* ffn_b2   = (const float*)d_in[13];
    const float* ln1_g    = (const float*)d_in[14];
    const float* ln1_b    = (const float*)d_in[15];
    const float* ln2_g    = (const float*)d_in[16];
    const float* ln2_b    = (const float*)d_in[17];
    const float* gat_wl   = (const float*)d_in[18];
    const float* gat_bl   = (const float*)d_in[19];
    const float* gat_wr   = (const float*)d_in[20];
    const float* gat_br   = (const float*)d_in[21];
    const float* gat_att  = (const float*)d_in[22];
    const float* gat_bias = (const float*)d_in[23];
    const float* W_q      = (const float*)d_in[24];
    const float* b_q      = (const float*)d_in[25];
    const float* pe       = (const float*)d_in[26];
    float* out = (float*)d_out;

    prep_w2t_kernel<<<(3 * 256 * 40 + 255) / 256, 256>>>(ffn_w2);
    csr_build_kernel<<<1, 1024>>>(edge_idx);

    tf_kernel<<<RTOT / TROWS, 64>>>(obs, pe,
        tf_wqkv, tf_bqkv, tf_wo, tf_bo,
        ffn_w1, ffn_b1, ffn_b2,
        ln1_g, ln1_b, ln2_g, ln2_b,
        W_emb1, b_emb1, W_emb2, b_emb2,
        gat_wl, gat_bl, gat_wr, gat_br);

    gat_kernel<<<(RTOT * 32) / 256, 256>>>(gat_att, gat_bias, W_q, b_q, out);
}

// round 4
// speedup vs baseline: 1.2424x; 1.2424x over previous
#include <cuda_runtime.h>
#include <cuda_bf16.h>
#include <math.h>

// Problem constants
#define BATCH 128
#define NNODE 1024
#define RTOT  (BATCH * NNODE)   // 131072
#define EEDGE 4096
#define DIM   40
#define SLEN  4
#define HID   128

// ---------------- scratch (__device__ globals; no allocation allowed) ----------------
__device__ float g_xl[(size_t)RTOT * HID];
__device__ float g_xr[(size_t)RTOT * HID];
__device__ float g_w2t[3 * 256 * 40];     // ffn_w2 transposed: [layer][k][d]
__device__ int   g_csr_off[NNODE + 1];
__device__ int   g_csr_src[EEDGE];

// ---------------- prep: transpose ffn_w2 ----------------
__global__ void prep_w2t_kernel(const float* __restrict__ w2) {
    int i = blockIdx.x * blockDim.x + threadIdx.x;
    if (i < 3 * 256 * 40) {
        int d = i % 40;
        int k = (i / 40) % 256;
        int l = i / (40 * 256);
        g_w2t[i] = w2[(size_t)l * 40 * 256 + (size_t)d * 256 + k];
    }
}

// ---------------- CSR build (single block, deterministic) ----------------
__global__ void csr_build_kernel(const int* __restrict__ edge_index) {
    __shared__ int cnt[NNODE];
    __shared__ int off[NNODE + 1];
    __shared__ int cur[NNODE];
    int t = threadIdx.x;            // 1024 threads
    cnt[t] = 0;
    __syncthreads();
    for (int e = t; e < EEDGE; e += 1024) {
        int dst = edge_index[EEDGE + e];
        atomicAdd(&cnt[dst], 1);
    }
    __syncthreads();
    if (t == 0) {
        off[0] = 0;
        for (int i = 0; i < NNODE; ++i) off[i + 1] = off[i] + cnt[i];
    }
    __syncthreads();
    cur[t] = off[t];
    __syncthreads();
    for (int e = t; e < EEDGE; e += 1024) {
        int src = edge_index[e];
        int dst = edge_index[EEDGE + e];
        int pos = atomicAdd(&cur[dst], 1);
        g_csr_src[pos] = src;
    }
    g_csr_off[t] = off[t];
    if (t == 0) g_csr_off[NNODE] = off[NNODE];
    __syncthreads();
    // canonicalize bucket order (value sort) -> deterministic summation order
    int lo = off[t], hi = off[t + 1];
    for (int i = lo + 1; i < hi; ++i) {
        int v = g_csr_src[i];
        int j = i - 1;
        while (j >= lo && g_csr_src[j] > v) { g_csr_src[j + 1] = g_csr_src[j]; --j; }
        g_csr_src[j + 1] = v;
    }
}

// ---------------- fused transformer + emb + xl/xr kernel ----------------
// Block: 128 threads = 32 rows x 4 tokens. The 4 token-threads of a row are
// consecutive lanes of one warp -> __syncwarp only.
// smem per row (stride 332 floats):
//   transformer phase: k,v per token at t*81 (+0:k, +40:v)
//   tail phase:        ret[0:192), emb1[192:320), emb2 overwrites [0:128)
#define TROWS 32
#define TOKS  81
#define RSTRIDE 332

__global__ __launch_bounds__(128) void tf_kernel(
    const float* __restrict__ obs, const float* __restrict__ pe,
    const float* __restrict__ wqkv_all, const float* __restrict__ bqkv_all,
    const float* __restrict__ wo_all,   const float* __restrict__ bo_all,
    const float* __restrict__ w1_all,   const float* __restrict__ b1_all,
    const float* __restrict__ b2_all,
    const float* __restrict__ ln1g_all, const float* __restrict__ ln1b_all,
    const float* __restrict__ ln2g_all, const float* __restrict__ ln2b_all,
    const float* __restrict__ Wemb1, const float* __restrict__ bemb1,
    const float* __restrict__ Wemb2, const float* __restrict__ bemb2,
    const float* __restrict__ gwl, const float* __restrict__ gbl,
    const float* __restrict__ gwr, const float* __restrict__ gbr)
{
    __shared__ float sm[TROWS * RSTRIDE];
    const int tid = threadIdx.x;
    const int rowloc = tid >> 2;
    const int t = tid & 3;
    const int r = blockIdx.x * TROWS + rowloc;
    float* rs = sm + rowloc * RSTRIDE;

    const float* xrow = obs + (size_t)r * 200;

    float h[40];
#pragma unroll
    for (int d = 0; d < 40; ++d)
        h[d] = __ldg(xrow + t * 40 + d) + __ldg(pe + t * 40 + d);

    for (int L = 0; L < 3; ++L) {
        const float* wqkv = wqkv_all + L * 4800;
        const float* bqkv = bqkv_all + L * 120;

        // ---- Q projection -> registers (4 outputs at a time, 4 chains) ----
        float q[40];
#pragma unroll
        for (int kk = 0; kk < 40; kk += 4) {
            float s0 = __ldg(bqkv + kk), s1 = __ldg(bqkv + kk + 1);
            float s2 = __ldg(bqkv + kk + 2), s3 = __ldg(bqkv + kk + 3);
            const float4* w = (const float4*)(wqkv + kk * 40);
#pragma unroll
            for (int d4 = 0; d4 < 10; ++d4) {
                float4 a0 = __ldg(w + d4), a1 = __ldg(w + 10 + d4);
                float4 a2 = __ldg(w + 20 + d4), a3 = __ldg(w + 30 + d4);
                float h0 = h[4*d4], h1 = h[4*d4+1], h2 = h[4*d4+2], h3 = h[4*d4+3];
                s0 += h0*a0.x + h1*a0.y + h2*a0.z + h3*a0.w;
                s1 += h0*a1.x + h1*a1.y + h2*a1.z + h3*a1.w;
                s2 += h0*a2.x + h1*a2.y + h2*a2.z + h3*a2.w;
                s3 += h0*a3.x + h1*a3.y + h2*a3.z + h3*a3.w;
            }
            q[kk] = s0; q[kk+1] = s1; q[kk+2] = s2; q[kk+3] = s3;
        }
        // ---- K,V projection -> smem ----
        float* kvp = rs + t * TOKS;
#pragma unroll
        for (int kk = 40; kk < 120; kk += 4) {
            float s0 = __ldg(bqkv + kk), s1 = __ldg(bqkv + kk + 1);
            float s2 = __ldg(bqkv + kk + 2), s3 = __ldg(bqkv + kk + 3);
            const float4* w = (const float4*)(wqkv + kk * 40);
#pragma unroll
            for (int d4 = 0; d4 < 10; ++d4) {
                float4 a0 = __ldg(w + d4), a1 = __ldg(w + 10 + d4);
                float4 a2 = __ldg(w + 20 + d4), a3 = __ldg(w + 30 + d4);
                float h0 = h[4*d4], h1 = h[4*d4+1], h2 = h[4*d4+2], h3 = h[4*d4+3];
                s0 += h0*a0.x + h1*a0.y + h2*a0.z + h3*a0.w;
                s1 += h0*a1.x + h1*a1.y + h2*a1.z + h3*a1.w;
                s2 += h0*a2.x + h1*a2.y + h2*a2.z + h3*a2.w;
                s3 += h0*a3.x + h1*a3.y + h2*a3.z + h3*a3.w;
            }
            kvp[kk - 40] = s0; kvp[kk - 39] = s1; kvp[kk - 38] = s2; kvp[kk - 37] = s3;
        }
        __syncwarp();

        // ---- attention (causal, 2 heads of 20); o overwrites q in-place ----
        const float scale = 0.22360679774997896f;  // 1/sqrt(20)
#pragma unroll
        for (int hh = 0; hh < 2; ++hh) {
            float sc[4];
            float mx = -1e30f;
#pragma unroll
            for (int j = 0; j < 4; ++j) {
                if (j <= t) {
                    const float* kj = rs + j * TOKS + hh * 20;
                    float s = 0.f;
#pragma unroll
                    for (int d = 0; d < 20; ++d)
                        s += q[hh*20 + d] * kj[d];
                    sc[j] = s * scale;
                    mx = fmaxf(mx, sc[j]);
                }
            }
            float den = 0.f;
#pragma unroll
            for (int j = 0; j < 4; ++j) {
                if (j <= t) { sc[j] = __expf(sc[j] - mx); den += sc[j]; }
                else sc[j] = 0.f;
            }
            float iden = 1.f / den;
#pragma unroll
            for (int d = 0; d < 20; ++d) {
                float a = sc[0] * rs[0*TOKS + 40 + hh*20 + d];
                a += sc[1] * rs[1*TOKS + 40 + hh*20 + d];
                a += sc[2] * rs[2*TOKS + 40 + hh*20 + d];
                a += sc[3] * rs[3*TOKS + 40 + hh*20 + d];
                q[hh*20 + d] = a * iden;   // q slot d no longer needed for this head
            }
        }
        __syncwarp();   // all smem kv reads done; next phase may rewrite

        // ---- output projection + residual + LN1 (q now holds attention out) ----
        const float* wo = wo_all + L * 1600;
        const float* bo = bo_all + L * 40;
        float nh[40];
#pragma unroll
        for (int d = 0; d < 40; d += 4) {
            float s0 = __ldg(bo + d),   s1 = __ldg(bo + d + 1);
            float s2 = __ldg(bo + d + 2), s3 = __ldg(bo + d + 3);
            const float4* w = (const float4*)(wo + d * 40);
#pragma unroll
            for (int e4 = 0; e4 < 10; ++e4) {
                float4 a0 = __ldg(w + e4), a1 = __ldg(w + 10 + e4);
                float4 a2 = __ldg(w + 20 + e4), a3 = __ldg(w + 30 + e4);
                float o0 = q[4*e4], o1 = q[4*e4+1], o2 = q[4*e4+2], o3 = q[4*e4+3];
                s0 += o0*a0.x + o1*a0.y + o2*a0.z + o3*a0.w;
                s1 += o0*a1.x + o1*a1.y + o2*a1.z + o3*a1.w;
                s2 += o0*a2.x + o1*a2.y + o2*a2.z + o3*a2.w;
                s3 += o0*a3.x + o1*a3.y + o2*a3.z + o3*a3.w;
            }
            nh[d] = h[d] + s0; nh[d+1] = h[d+1] + s1;
            nh[d+2] = h[d+2] + s2; nh[d+3] = h[d+3] + s3;
        }
        {
            float mean = 0.f;
#pragma unroll
            for (int d = 0; d < 40; ++d) mean += nh[d];
            mean *= (1.f / 40.f);
            float var = 0.f;
#pragma unroll
            for (int d = 0; d < 40; ++d) { float dv = nh[d] - mean; var += dv * dv; }
            var *= (1.f / 40.f);
            float rstd = rsqrtf(var + 1e-6f);
#pragma unroll
            for (int d = 0; d < 40; ++d)
                h[d] = (nh[d] - mean) * rstd * __ldg(ln1g_all + L*40 + d) + __ldg(ln1b_all + L*40 + d);
        }

        // ---- FFN (4 hidden units at a time; rank-1 updates into nh) ----
        const float* w1  = w1_all + L * 10240;
        const float* w2t = g_w2t  + L * 10240;
        const float* b1  = b1_all + L * 256;
#pragma unroll
        for (int d = 0; d < 40; ++d) nh[d] = h[d] + __ldg(b2_all + L * 40 + d);
        for (int k = 0; k < 256; k += 4) {
            float u0 = __ldg(b1 + k),   u1 = __ldg(b1 + k + 1);
            float u2 = __ldg(b1 + k + 2), u3 = __ldg(b1 + k + 3);
            const float4* wa = (const float4*)(w1 + k * 40);
#pragma unroll
            for (int d4 = 0; d4 < 10; ++d4) {
                float4 a0 = __ldg(wa + d4), a1 = __ldg(wa + 10 + d4);
                float4 a2 = __ldg(wa + 20 + d4), a3 = __ldg(wa + 30 + d4);
                float h0 = h[4*d4], h1 = h[4*d4+1], h2 = h[4*d4+2], h3 = h[4*d4+3];
                u0 += h0*a0.x + h1*a0.y + h2*a0.z + h3*a0.w;
                u1 += h0*a1.x + h1*a1.y + h2*a1.z + h3*a1.w;
                u2 += h0*a2.x + h1*a2.y + h2*a2.z + h3*a2.w;
                u3 += h0*a3.x + h1*a3.y + h2*a3.z + h3*a3.w;
            }
            u0 = fmaxf(u0, 0.f); u1 = fmaxf(u1, 0.f);
            u2 = fmaxf(u2, 0.f); u3 = fmaxf(u3, 0.f);
            const float4* wb = (const float4*)(w2t + k * 40);
#pragma unroll
            for (int d4 = 0; d4 < 10; ++d4) {
                float4 b0 = __ldg(wb + d4), bb1 = __ldg(wb + 10 + d4);
                float4 b2v = __ldg(wb + 20 + d4), b3 = __ldg(wb + 30 + d4);
                nh[4*d4]   += u0*b0.x + u1*bb1.x + u2*b2v.x + u3*b3.x;
                nh[4*d4+1] += u0*b0.y + u1*bb1.y + u2*b2v.y + u3*b3.y;
                nh[4*d4+2] += u0*b0.z + u1*bb1.z + u2*b2v.z + u3*b3.z;
                nh[4*d4+3] += u0*b0.w + u1*bb1.w + u2*b2v.w + u3*b3.w;
            }
        }
        {
            float mean = 0.f;
#pragma unroll
            for (int d = 0; d < 40; ++d) mean += nh[d];
            mean *= (1.f / 40.f);
            float var = 0.f;
#pragma unroll
            for (int d = 0; d < 40; ++d) { float dv = nh[d] - mean; var += dv * dv; }
            var *= (1.f / 40.f);
            float rstd = rsqrtf(var + 1e-6f);
#pragma unroll
            for (int d = 0; d < 40; ++d)
                h[d] = (nh[d] - mean) * rstd * __ldg(ln2g_all + L*40 + d) + __ldg(ln2b_all + L*40 + d);
        }
    }

    // ---- emb1 / emb2 / xl / xr tail ----
    __syncwarp();
#pragma unroll
    for (int d = 0; d < 40; ++d) rs[t * 40 + d] = h[d];          // ret[0:160]
#pragma unroll
    for (int j = 0; j < 8; ++j)                                  // ret[160:192] = current_obs
        rs[160 + t * 8 + j] = __ldg(xrow + 160 + t * 8 + j);
    __syncwarp();

#pragma unroll 2
    for (int oi = 0; oi < 32; oi += 4) {                         // emb1: 192 -> 128, relu
        int oo = t * 32 + oi;
        float s0 = __ldg(bemb1 + oo),   s1 = __ldg(bemb1 + oo + 1);
        float s2 = __ldg(bemb1 + oo + 2), s3 = __ldg(bemb1 + oo + 3);
        const float4* w = (const float4*)(Wemb1 + (size_t)oo * 192);
#pragma unroll
        for (int j4 = 0; j4 < 48; ++j4) {
            float4 a0 = __ldg(w + j4), a1 = __ldg(w + 48 + j4);
            float4 a2 = __ldg(w + 96 + j4), a3 = __ldg(w + 144 + j4);
            float4 xv = *(const float4*)(rs + 4 * j4);
            s0 += xv.x*a0.x + xv.y*a0.y + xv.z*a0.z + xv.w*a0.w;
            s1 += xv.x*a1.x + xv.y*a1.y + xv.z*a1.z + xv.w*a1.w;
            s2 += xv.x*a2.x + xv.y*a2.y + xv.z*a2.z + xv.w*a2.w;
            s3 += xv.x*a3.x + xv.y*a3.y + xv.z*a3.z + xv.w*a3.w;
        }
        rs[192 + oo]     = fmaxf(s0, 0.f);
        rs[192 + oo + 1] = fmaxf(s1, 0.f);
        rs[192 + oo + 2] = fmaxf(s2, 0.f);
        rs[192 + oo + 3] = fmaxf(s3, 0.f);
    }
    __syncwarp();   // emb1 complete; ret region [0:192) is now dead

    // emb2: 128 -> 128, relu. Reads emb1 at [192:320), writes directly into
    // the dead ret region [0:128). Disjoint regions -> safe mid-loop.
#pragma unroll 2
    for (int oi = 0; oi < 32; oi += 4) {
        int oo = t * 32 + oi;
        float s0 = __ldg(bemb2 + oo),   s1 = __ldg(bemb2 + oo + 1);
        float s2 = __ldg(bemb2 + oo + 2), s3 = __ldg(bemb2 + oo + 3);
        const float4* w = (const float4*)(Wemb2 + (size_t)oo * 128);
#pragma unroll
        for (int j4 = 0; j4 < 32; ++j4) {
            float4 a0 = __ldg(w + j4), a1 = __ldg(w + 32 + j4);
            float4 a2 = __ldg(w + 64 + j4), a3 = __ldg(w + 96 + j4);
            float4 xv = *(const float4*)(rs + 192 + 4 * j4);
            s0 += xv.x*a0.x + xv.y*a0.y + xv.z*a0.z + xv.w*a0.w;
            s1 += xv.x*a1.x + xv.y*a1.y + xv.z*a1.z + xv.w*a1.w;
            s2 += xv.x*a2.x + xv.y*a2.y + xv.z*a2.z + xv.w*a2.w;
            s3 += xv.x*a3.x + xv.y*a3.y + xv.z*a3.z + xv.w*a3.w;
        }
        rs[oo]     = fmaxf(s0, 0.f);
        rs[oo + 1] = fmaxf(s1, 0.f);
        rs[oo + 2] = fmaxf(s2, 0.f);
        rs[oo + 3] = fmaxf(s3, 0.f);
    }
    __syncwarp();

#pragma unroll 2
    for (int oi = 0; oi < 32; oi += 2) {                         // xl / xr projections
        int oo = t * 32 + oi;
        float sl0 = __ldg(gbl + oo), sl1 = __ldg(gbl + oo + 1);
        float sr0 = __ldg(gbr + oo), sr1 = __ldg(gbr + oo + 1);
        const float4* wl = (const float4*)(gwl + (size_t)oo * 128);
        const float4* wr = (const float4*)(gwr + (size_t)oo * 128);
#pragma unroll
        for (int j4 = 0; j4 < 32; ++j4) {
            float4 a0 = __ldg(wl + j4),      a1 = __ldg(wl + 32 + j4);
            float4 b0 = __ldg(wr + j4),      b1v = __ldg(wr + 32 + j4);
            float4 xv = *(const float4*)(rs + 4 * j4);
            sl0 += xv.x*a0.x + xv.y*a0.y + xv.z*a0.z + xv.w*a0.w;
            sl1 += xv.x*a1.x + xv.y*a1.y + xv.z*a1.z + xv.w*a1.w;
            sr0 += xv.x*b0.x + xv.y*b0.y + xv.z*b0.z + xv.w*b0.w;
            sr1 += xv.x*b1v.x + xv.y*b1v.y + xv.z*b1v.z + xv.w*b1v.w;
        }
        g_xl[(size_t)r * 128 + oo]     = sl0;
        g_xl[(size_t)r * 128 + oo + 1] = sl1;
        g_xr[(size_t)r * 128 + oo]     = sr0;
        g_xr[(size_t)r * 128 + oo + 1] = sr1;
    }
}

// ---------------- GAT gather + final linear (warp per row, online softmax) ----------------
__global__ void gat_kernel(const float* __restrict__ gat_att,
                           const float* __restrict__ gat_bias,
                           const float* __restrict__ Wq,
                           const float* __restrict__ bq,
                           float* __restrict__ out)
{
    const int warp = (blockIdx.x * blockDim.x + threadIdx.x) >> 5;
    const int lane = threadIdx.x & 31;
    if (warp >= RTOT) return;
    const int r = warp;
    const int b = r >> 10;
    const int n = r & 1023;

    float xrv[4], attv[4], m[4], l[4], acc[4];
#pragma unroll
    for (int hh = 0; hh < 4; ++hh) {
        xrv[hh]  = g_xr[(size_t)r * 128 + hh * 32 + lane];
        attv[hh] = __ldg(gat_att + hh * 32 + lane);
        m[hh] = -1e30f; l[hh] = 0.f; acc[hh] = 0.f;
    }
    const int lo = g_csr_off[n], hi = g_csr_off[n + 1];
    for (int it = -1; it < hi - lo; ++it) {
        const int srcn = (it < 0) ? n : g_csr_src[lo + it];   // self-loop first, then sorted edges
        const float* xlp = g_xl + ((size_t)(b * 1024 + srcn)) * 128;
        float xlv[4], ev[4];
#pragma unroll
        for (int hh = 0; hh < 4; ++hh) {
            xlv[hh] = xlp[hh * 32 + lane];
            float mm = xlv[hh] + xrv[hh];
            mm = (mm > 0.f) ? mm : 0.2f * mm;                 // leaky_relu(0.2)
            float p = mm * attv[hh];
#pragma unroll
            for (int s = 16; s > 0; s >>= 1) p += __shfl_xor_sync(0xffffffffu, p, s);
            ev[hh] = p;
        }
#pragma unroll
        for (int hh = 0; hh < 4; ++hh) {
            float nm  = fmaxf(m[hh], ev[hh]);
            float pe_ = expf(ev[hh] - nm);
            float sc  = expf(m[hh] - nm);
            l[hh]   = l[hh] * sc + pe_;
            acc[hh] = acc[hh] * sc + pe_ * xlv[hh];
            m[hh] = nm;
        }
    }
    float h2[4];
#pragma unroll
    for (int hh = 0; hh < 4; ++hh)
        h2[hh] = acc[hh] / l[hh] + __ldg(gat_bias + hh * 32 + lane);

#pragma unroll
    for (int a = 0; a < 8; ++a) {
        float p = 0.f;
#pragma unroll
        for (int hh = 0; hh < 4; ++hh)
            p += h2[hh] * __ldg(Wq + a * 128 + hh * 32 + lane);
#pragma unroll
        for (int s = 16; s > 0; s >>= 1) p += __shfl_xor_sync(0xffffffffu, p, s);
        if (lane == 0) out[(size_t)r * 8 + a] = p + __ldg(bq + a);
    }
}

// ---------------- launch ----------------
extern "C" void kernel_launch(void* const* d_in, const int* in_sizes, int n_in,
                              void* d_out, int out_size) {
    const float* obs      = (const float*)d_in[0];
    const int*   edge_idx = (const int*)  d_in[1];
    const float* W_emb1   = (const float*)d_in[2];
    const float* b_emb1   = (const float*)d_in[3];
    const float* W_emb2   = (const float*)d_in[4];
    const float* b_emb2   = (const float*)d_in[5];
    const float* tf_wqkv  = (const float*)d_in[6];
    const float* tf_bqkv  = (const float*)d_in[7];
    const float* tf_wo    = (const float*)d_in[8];
    const float* tf_bo    = (const float*)d_in[9];
    const float* ffn_w1   = (const float*)d_in[10];
    const float* ffn_b1   = (const float*)d_in[11];
    const float* ffn_w2   = (const float*)d_in[12];
    const float* ffn_b2   = (const float*)d_in[13];
    const float* ln1_g    = (const float*)d_in[14];
    const float* ln1_b    = (const float*)d_in[15];
    const float* ln2_g    = (const float*)d_in[16];
    const float* ln2_b    = (const float*)d_in[17];
    const float* gat_wl   = (const float*)d_in[18];
    const float* gat_bl   = (const float*)d_in[19];
    const float* gat_wr   = (const float*)d_in[20];
    const float* gat_br   = (const float*)d_in[21];
    const float* gat_att  = (const float*)d_in[22];
    const float* gat_bias = (const float*)d_in[23];
    const float* W_q      = (const float*)d_in[24];
    const float* b_q      = (const float*)d_in[25];
    const float* pe       = (const float*)d_in[26];
    float* out = (float*)d_out;

    prep_w2t_kernel<<<(3 * 256 * 40 + 255) / 256, 256>>>(ffn_w2);
    csr_build_kernel<<<1, 1024>>>(edge_idx);

    tf_kernel<<<RTOT / TROWS, 128>>>(obs, pe,
        tf_wqkv, tf_bqkv, tf_wo, tf_bo,
        ffn_w1, ffn_b1, ffn_b2,
        ln1_g, ln1_b, ln2_g, ln2_b,
        W_emb1, b_emb1, W_emb2, b_emb2,
        gat_wl, gat_bl, gat_wr, gat_br);

    gat_kernel<<<(RTOT * 32) / 256, 256>>>(gat_att, gat_bias, W_q, b_q, out);
}